// round 12
// baseline (speedup 1.0000x reference)
#include <cuda_runtime.h>
#include <cuda_fp16.h>
#include <cstdint>

// GraphSAGE 2-layer, D=64 — persistent kernel <<<148, 1024>>>, padded-CSR
// quarter-warp gather (fp16 rows) + f32x2 combine (2-node tile).
//   layer: out = h @ W_self + mean_{in}(h) @ W_neigh + b
//   h1 = relu(layer1(x)); out = layer2(h1)
//
// Phases / 8 grid barriers (even count -> graph-replay safe):
//   0 x->g_x16 (+zero pad rows), zero cnt | 1 hist(+rank) | 2a scan | 2b base+pad
//   3 fill | 4 gather1 | 5 combine1(relu -> g_h1 + g_h116) | 6 gather2 | 7 combine2

#define D 64
#define MAXN 50048
#define MAXEP 1200000
#define NBLK 148
#define NTHR 1024
#define NGROUP (NTHR / 256)

__device__ __half g_x16[MAXN * D];    // fp16 x rows, row n zeroed (sentinel)
__device__ __half g_h116[MAXN * D];   // fp16 h1 rows, row n zeroed
__device__ float  g_h1[MAXN * D];     // fp32 h1 (self path / GEMM)
__device__ float  g_mean[MAXN * D];   // neighbor means (fp32)
__device__ int    g_cnt[MAXN];
__device__ int    g_rowstart[MAXN];
__device__ int    g_rank[MAXEP];
__device__ int    g_edge[MAXEP];
__device__ int    g_part[NBLK];
__device__ unsigned g_bar_count;
__device__ volatile unsigned g_bar_sense;

typedef unsigned long long u64;

__device__ __forceinline__ u64 pk2(float a, float b) {
    u64 r;
    asm("mov.b64 %0, {%1, %2};" : "=l"(r)
        : "r"(__float_as_uint(a)), "r"(__float_as_uint(b)));
    return r;
}
__device__ __forceinline__ void upk2(u64 v, float& a, float& b) {
    unsigned int x, y;
    asm("mov.b64 {%0, %1}, %2;" : "=r"(x), "=r"(y) : "l"(v));
    a = __uint_as_float(x);
    b = __uint_as_float(y);
}
__device__ __forceinline__ u64 fma2(u64 a, u64 b, u64 c) {
    u64 d;
    asm("fma.rn.f32x2 %0, %1, %2, %3;" : "=l"(d) : "l"(a), "l"(b), "l"(c));
    return d;
}

// Sense-reversing grid barrier (validated R8-R11).
__device__ __forceinline__ void grid_barrier(unsigned& sense) {
    __syncthreads();
    if (threadIdx.x == 0) {
        sense ^= 1u;
        __threadfence();
        unsigned arrived = atomicAdd(&g_bar_count, 1u) + 1u;
        if (arrived == NBLK) {
            g_bar_count = 0;
            __threadfence();
            g_bar_sense = sense;
        } else {
            while (g_bar_sense != sense) __nanosleep(32);
        }
        __threadfence();
    }
    __syncthreads();
}

// ---------------------------------------------------------------------------
// Gather v7: QUARTER-WARP per node (4 concurrent nodes per warp), fp16 rows.
// Lane (0..7) owns 8 columns via one uint4 (16 B) -> 8 lanes x 16 B = one
// 128 B line per neighbor row. Inner loop: pipelined 4-batches (indices for
// batch j+1 loaded while batch j's rows are in flight). Branch-free body;
// sentinel edges -> zero row n. Degrees padded to 8 (multiple of 4).
// ---------------------------------------------------------------------------
__device__ void gather_phase(const __half* __restrict__ feat, int n) {
    const uint4* __restrict__ base = reinterpret_cast<const uint4*>(feat);
    const int nqw = NBLK * (NTHR / 8);
    const int gqw = blockIdx.x * (NTHR / 8) + (threadIdx.x >> 3);
    const int lane = threadIdx.x & 7;

    for (int node = gqw; node < n; node += nqw) {
        int start = g_rowstart[node];
        int cnt   = g_cnt[node];
        int degp  = (cnt + 7) & ~7;          // multiple of 8 (hence of 4)

        float a0 = 0.f, a1 = 0.f, a2 = 0.f, a3 = 0.f;
        float a4 = 0.f, a5 = 0.f, a6 = 0.f, a7 = 0.f;
        const int* ep = g_edge + start;

        if (degp > 0) {
            int i0 = __ldg(ep + 0);
            int i1 = __ldg(ep + 1);
            int i2 = __ldg(ep + 2);
            int i3 = __ldg(ep + 3);

            for (int j = 0; j < degp; j += 4) {
                uint4 v0 = __ldg(base + (size_t)i0 * 8 + lane);
                uint4 v1 = __ldg(base + (size_t)i1 * 8 + lane);
                uint4 v2 = __ldg(base + (size_t)i2 * 8 + lane);
                uint4 v3 = __ldg(base + (size_t)i3 * 8 + lane);

                bool more = (j + 4) < degp;
                int j4 = more ? (j + 4) : 0;
                i0 = __ldg(ep + j4 + 0);
                i1 = __ldg(ep + j4 + 1);
                i2 = __ldg(ep + j4 + 2);
                i3 = __ldg(ep + j4 + 3);

#pragma unroll
                for (int u = 0; u < 4; u++) {
                    uint4 v = (u == 0) ? v0 : (u == 1) ? v1 : (u == 2) ? v2 : v3;
                    __half2* h = reinterpret_cast<__half2*>(&v);
                    float2 f0 = __half22float2(h[0]);
                    float2 f1 = __half22float2(h[1]);
                    float2 f2 = __half22float2(h[2]);
                    float2 f3 = __half22float2(h[3]);
                    a0 += f0.x; a1 += f0.y; a2 += f1.x; a3 += f1.y;
                    a4 += f2.x; a5 += f2.y; a6 += f3.x; a7 += f3.y;
                }
            }
        }

        float inv = 1.0f / fmaxf((float)cnt, 1.0f);
        float* mp = g_mean + (size_t)node * D + lane * 8;
        *reinterpret_cast<float4*>(mp) =
            make_float4(a0 * inv, a1 * inv, a2 * inv, a3 * inv);
        *reinterpret_cast<float4*>(mp + 4) =
            make_float4(a4 * inv, a5 * inv, a6 * inv, a7 * inv);
    }
}

// ---------------------------------------------------------------------------
// Combine: out = h@W_self + mean@W_neigh + b [+relu]; f32x2, 2-node tile.
// 256-thread group = 16 col-groups x 16 node-groups of 2 nodes (32 nodes).
// ---------------------------------------------------------------------------
template <bool RELU, bool TO_H116>
__device__ void combine_phase(const float* __restrict__ h,
                              const float* __restrict__ Wself,
                              const float* __restrict__ Wneigh,
                              const float* __restrict__ bias,
                              float* __restrict__ out, int n,
                              float* sWs, float* sWn) {
    int tid = threadIdx.x;
    for (int i = tid; i < D * D / 4; i += NTHR) {
        reinterpret_cast<float4*>(sWs)[i] =
            reinterpret_cast<const float4*>(Wself)[i];
        reinterpret_cast<float4*>(sWn)[i] =
            reinterpret_cast<const float4*>(Wneigh)[i];
    }
    __syncthreads();

    int sub = tid & 255;
    int grp = tid >> 8;
    int cg = sub & 15;
    int c0 = cg * 4;
    int ng = sub >> 4;
    int ntiles = (n + 31) / 32;

    u64 b01 = pk2(__ldg(bias + c0 + 0), __ldg(bias + c0 + 1));
    u64 b23 = pk2(__ldg(bias + c0 + 2), __ldg(bias + c0 + 3));

    for (int tile = blockIdx.x * NGROUP + grp; tile < ntiles;
         tile += NBLK * NGROUP) {
        int nbase = tile * 32 + ng * 2;

        bool valid[2];
#pragma unroll
        for (int i = 0; i < 2; i++) valid[i] = (nbase + i) < n;

        u64 acc[2][2];
#pragma unroll
        for (int i = 0; i < 2; i++) { acc[i][0] = b01; acc[i][1] = b23; }

#pragma unroll 4
        for (int k0 = 0; k0 < D; k0 += 4) {
            float4 xv[2], mv[2];
#pragma unroll
            for (int i = 0; i < 2; i++) {
                if (valid[i]) {
                    xv[i] = *reinterpret_cast<const float4*>(
                        h + (size_t)(nbase + i) * D + k0);
                    mv[i] = *reinterpret_cast<const float4*>(
                        g_mean + (size_t)(nbase + i) * D + k0);
                } else {
                    xv[i] = make_float4(0.f, 0.f, 0.f, 0.f);
                    mv[i] = make_float4(0.f, 0.f, 0.f, 0.f);
                }
            }
#pragma unroll
            for (int j = 0; j < 4; j++) {
                int k = k0 + j;
                float4 ws = *reinterpret_cast<const float4*>(sWs + k * D + c0);
                float4 wn = *reinterpret_cast<const float4*>(sWn + k * D + c0);
                u64 ws01 = pk2(ws.x, ws.y), ws23 = pk2(ws.z, ws.w);
                u64 wn01 = pk2(wn.x, wn.y), wn23 = pk2(wn.z, wn.w);
#pragma unroll
                for (int i = 0; i < 2; i++) {
                    float xk = (j == 0) ? xv[i].x : (j == 1) ? xv[i].y
                              : (j == 2) ? xv[i].z : xv[i].w;
                    float mk = (j == 0) ? mv[i].x : (j == 1) ? mv[i].y
                              : (j == 2) ? mv[i].z : mv[i].w;
                    u64 xx = pk2(xk, xk);
                    u64 mm = pk2(mk, mk);
                    acc[i][0] = fma2(xx, ws01, acc[i][0]);
                    acc[i][0] = fma2(mm, wn01, acc[i][0]);
                    acc[i][1] = fma2(xx, ws23, acc[i][1]);
                    acc[i][1] = fma2(mm, wn23, acc[i][1]);
                }
            }
        }

#pragma unroll
        for (int i = 0; i < 2; i++) {
            if (!valid[i]) continue;
            float a0, a1, a2, a3;
            upk2(acc[i][0], a0, a1);
            upk2(acc[i][1], a2, a3);
            if (RELU) {
                a0 = fmaxf(a0, 0.f); a1 = fmaxf(a1, 0.f);
                a2 = fmaxf(a2, 0.f); a3 = fmaxf(a3, 0.f);
            }
            *reinterpret_cast<float4*>(out + (size_t)(nbase + i) * D + c0) =
                make_float4(a0, a1, a2, a3);
            if (TO_H116) {
                __half2* p = reinterpret_cast<__half2*>(
                    g_h116 + (size_t)(nbase + i) * D + c0);
                p[0] = __floats2half2_rn(a0, a1);
                p[1] = __floats2half2_rn(a2, a3);
            }
        }
    }
}

// ---------------------------------------------------------------------------
__global__ void __launch_bounds__(NTHR, 1)
sage_kernel(const float* __restrict__ x,
            const int* __restrict__ src,
            const int* __restrict__ dst,
            const float* __restrict__ W1s, const float* __restrict__ W1n,
            const float* __restrict__ b1,
            const float* __restrict__ W2s, const float* __restrict__ W2n,
            const float* __restrict__ b2,
            float* __restrict__ out, int n, int E) {
    __shared__ float sWs[D * D];
    __shared__ float sWn[D * D];

    unsigned sense = 0;
    const int tid_g = blockIdx.x * NTHR + threadIdx.x;
    const int gstride = NBLK * NTHR;
    const int t = threadIdx.x;

    // ---- phase 0: x -> fp16 table, zero sentinel rows, zero counters ----
    {
        int total4 = n * (D / 4);
        for (int i = tid_g; i < total4; i += gstride) {
            float4 v = reinterpret_cast<const float4*>(x)[i];
            reinterpret_cast<__half2*>(g_x16)[i * 2 + 0] = __floats2half2_rn(v.x, v.y);
            reinterpret_cast<__half2*>(g_x16)[i * 2 + 1] = __floats2half2_rn(v.z, v.w);
        }
        for (int i = tid_g; i < n; i += gstride) g_cnt[i] = 0;
        if (blockIdx.x == 0 && t < D / 2) {
            __half2 z = __floats2half2_rn(0.f, 0.f);
            reinterpret_cast<__half2*>(g_x16 + (size_t)n * D)[t] = z;
            reinterpret_cast<__half2*>(g_h116 + (size_t)n * D)[t] = z;
        }
    }
    grid_barrier(sense);

    // ---- phase 1: histogram + rank capture ----
    for (int e = tid_g; e < E; e += gstride)
        g_rank[e] = atomicAdd(&g_cnt[__ldg(dst + e)], 1);
    grid_barrier(sense);

    // ---- phase 2a: block-local exclusive scan of padded counts ----
    int* s = reinterpret_cast<int*>(sWs);
    const int chunk = (n + NBLK - 1) / NBLK;      // 338 <= NTHR
    const int node = blockIdx.x * chunk + t;
    int padded = 0;
    if (t < chunk && node < n) padded = (g_cnt[node] + 7) & ~7;
    s[t] = padded;
    __syncthreads();
    for (int off = 1; off < NTHR; off <<= 1) {
        int v = (t >= off) ? s[t - off] : 0;
        __syncthreads();
        s[t] += v;
        __syncthreads();
    }
    int excl = s[t] - padded;
    if (t == NTHR - 1) g_part[blockIdx.x] = s[NTHR - 1];
    grid_barrier(sense);

    // ---- phase 2b: global base + rowstart + sentinel padding edges ----
    {
        int* sp = reinterpret_cast<int*>(sWn);
        if (t < NBLK) sp[t] = g_part[t];
        __syncthreads();
        int base = 0;
        for (int b = 0; b < blockIdx.x; b++) base += sp[b];
        if (t < chunk && node < n) {
            int rs = base + excl;
            g_rowstart[node] = rs;
            int cnt = g_cnt[node];
            int degp = (cnt + 7) & ~7;
            for (int j = cnt; j < degp; j++) g_edge[rs + j] = n;
        }
    }
    grid_barrier(sense);

    // ---- phase 3: fill CSR (atomic-free) ----
    for (int e = tid_g; e < E; e += gstride) {
        int d = __ldg(dst + e);
        g_edge[g_rowstart[d] + g_rank[e]] = __ldg(src + e);
    }
    grid_barrier(sense);

    // ---- phase 4: gather layer 1 (fp16 x rows) ----
    gather_phase(g_x16, n);
    grid_barrier(sense);

    // ---- phase 5: combine layer 1 (relu) -> g_h1 fp32 + g_h116 fp16 ----
    combine_phase<true, true>(x, W1s, W1n, b1, g_h1, n, sWs, sWn);
    grid_barrier(sense);

    // ---- phase 6: gather layer 2 (fp16 h1 rows) ----
    gather_phase(g_h116, n);
    grid_barrier(sense);

    // ---- phase 7: combine layer 2 -> out ----
    combine_phase<false, false>(g_h1, W2s, W2n, b2, out, n, sWs, sWn);
}

// ---------------------------------------------------------------------------
extern "C" void kernel_launch(void* const* d_in, const int* in_sizes, int n_in,
                              void* d_out, int out_size) {
    const float* x        = (const float*)d_in[0];
    const int*   src      = (const int*)d_in[1];
    const int*   dst      = (const int*)d_in[2];
    const float* W1_self  = (const float*)d_in[3];
    const float* W1_neigh = (const float*)d_in[4];
    const float* b1       = (const float*)d_in[5];
    const float* W2_self  = (const float*)d_in[6];
    const float* W2_neigh = (const float*)d_in[7];
    const float* b2       = (const float*)d_in[8];
    float* out = (float*)d_out;

    int n = in_sizes[0] / D;
    int E = in_sizes[1];

    sage_kernel<<<NBLK, NTHR>>>(x, src, dst,
                                W1_self, W1_neigh, b1,
                                W2_self, W2_neigh, b2,
                                out, n, E);
}

// round 13
// speedup vs baseline: 1.7021x; 1.7021x over previous
#include <cuda_runtime.h>
#include <cuda_fp16.h>
#include <cstdint>

// GraphSAGE 2-layer, D=64 — persistent kernel <<<148, 768>>>:
//   R11 half-warp padded-CSR gather (fp16 rows, 8-deep pipelined)
//   + NEW: combine as fp16 mma.sync GEMM  out = [feat|mean] @ [Wself;Wneigh] + b
//
// Feature table g_A[MAXN+1 rows][128 cols] fp16:
//   cols 0..63  = features (x for layer 1, h1 after combine1)
//   cols 64..127= neighbor mean (written by gather each layer)
//   row n       = all-zero sentinel for padded CSR edges
//
// Phases / 8 grid barriers:
//   0 x->g_A(+zero row n), zero cnt | 1 hist(+rank) | 2a scan | 2b base+pad
//   3 fill | 4 gather1 | 5 combine1(relu, h1->g_A) | 6 gather2 | 7 combine2(->out fp32)

#define D 64
#define AC 128                      // A-table columns
#define MAXN 50048
#define MAXEP 1200000
#define NBLK 148
#define NTHR 768
#define NWARP (NTHR / 32)
#define BSTRIDE 136                 // smem B row stride in halves (bank-spread)

__device__ __half g_A[MAXN * AC];
__device__ int    g_cnt[MAXN];
__device__ int    g_rowstart[MAXN];
__device__ int    g_rank[MAXEP];
__device__ int    g_edge[MAXEP];
__device__ int    g_part[NBLK];
__device__ unsigned g_bar_count;
__device__ volatile unsigned g_bar_sense;

// Sense-reversing grid barrier (validated R8-R12).
__device__ __forceinline__ void grid_barrier(unsigned& sense) {
    __syncthreads();
    if (threadIdx.x == 0) {
        sense ^= 1u;
        __threadfence();
        unsigned arrived = atomicAdd(&g_bar_count, 1u) + 1u;
        if (arrived == NBLK) {
            g_bar_count = 0;
            __threadfence();
            g_bar_sense = sense;
        } else {
            while (g_bar_sense != sense) __nanosleep(32);
        }
        __threadfence();
    }
    __syncthreads();
}

__device__ __forceinline__ void mma16816(float d[4],
                                         uint32_t a0, uint32_t a1,
                                         uint32_t a2, uint32_t a3,
                                         uint32_t b0, uint32_t b1) {
    asm volatile(
        "mma.sync.aligned.m16n8k16.row.col.f32.f16.f16.f32 "
        "{%0,%1,%2,%3}, {%4,%5,%6,%7}, {%8,%9}, {%0,%1,%2,%3};"
        : "+f"(d[0]), "+f"(d[1]), "+f"(d[2]), "+f"(d[3])
        : "r"(a0), "r"(a1), "r"(a2), "r"(a3), "r"(b0), "r"(b1));
}

// ---------------------------------------------------------------------------
// Gather (R11 design): HALF-WARP per node, fp16 rows from g_A cols 0..63.
// 8-deep row-load batches, next-stripe index prefetch, sentinel row n.
// Writes MEAN (fp16) to g_A cols 64..127.
// ---------------------------------------------------------------------------
__device__ void gather_phase(int n) {
    const uint2* __restrict__ base = reinterpret_cast<const uint2*>(g_A);
    const int nhw = NBLK * (NTHR / 16);
    const int ghw = blockIdx.x * (NTHR / 16) + (threadIdx.x >> 4);
    const int lane = threadIdx.x & 15;

    for (int node = ghw; node < n; node += nhw) {
        int start = g_rowstart[node];
        int cnt   = g_cnt[node];
        int degp  = (cnt + 7) & ~7;

        float a0 = 0.f, a1 = 0.f, a2 = 0.f, a3 = 0.f;
        const int* ep = g_edge + start;

        if (degp > 0) {
            int idx[8];
#pragma unroll
            for (int u = 0; u < 8; u++) idx[u] = __ldg(ep + u);

            for (int j = 0; j < degp; j += 8) {
                uint2 v[8];
#pragma unroll
                for (int u = 0; u < 8; u++)
                    v[u] = __ldg(base + (size_t)idx[u] * 32 + lane);

                bool more = (j + 8) < degp;
                int nidx[8];
#pragma unroll
                for (int u = 0; u < 8; u++)
                    nidx[u] = more ? __ldg(ep + j + 8 + u) : 0;

#pragma unroll
                for (int u = 0; u < 8; u++) {
                    float2 fa = __half22float2(
                        *reinterpret_cast<__half2*>(&v[u].x));
                    float2 fb = __half22float2(
                        *reinterpret_cast<__half2*>(&v[u].y));
                    a0 += fa.x; a1 += fa.y; a2 += fb.x; a3 += fb.y;
                }
#pragma unroll
                for (int u = 0; u < 8; u++) idx[u] = nidx[u];
            }
        }

        float inv = 1.0f / fmaxf((float)cnt, 1.0f);
        __half2 m0 = __floats2half2_rn(a0 * inv, a1 * inv);
        __half2 m1 = __floats2half2_rn(a2 * inv, a3 * inv);
        uint2 mw;
        mw.x = *reinterpret_cast<unsigned*>(&m0);
        mw.y = *reinterpret_cast<unsigned*>(&m1);
        // mean cols 64..127: uint2 slot = 16 + lane within the 32-uint2 row
        *reinterpret_cast<uint2*>(
            const_cast<uint2*>(base) + (size_t)node * 32 + 16 + lane) = mw;
    }
}

// ---------------------------------------------------------------------------
// Combine via mma.sync: warp handles one 16-node tile, N=64, K=128.
//   A[16][128] fp16 from g_A (rows clamped to sentinel n), B[128][64] fp16
//   staged transposed in smem (sB[nn][k], stride BSTRIDE).
// OUT16: write relu(out) as fp16 into g_A cols 0..63 (layer 1 h1).
// else : write out fp32 to `out` (layer 2).
// ---------------------------------------------------------------------------
template <bool RELU, bool OUT16>
__device__ void combine_phase(const float* __restrict__ Wself,
                              const float* __restrict__ Wneigh,
                              const float* __restrict__ bias,
                              float* __restrict__ out, int n,
                              __half* sB) {
    const int t = threadIdx.x;
    // Stage B transposed: sB[nn*BSTRIDE + k] = Wself[k][nn]; +64 for Wneigh.
    for (int i = t; i < D * D; i += NTHR) {
        int k = i >> 6, nn = i & 63;
        sB[nn * BSTRIDE + k]      = __float2half(__ldg(Wself + i));
        sB[nn * BSTRIDE + 64 + k] = __float2half(__ldg(Wneigh + i));
    }
    __syncthreads();

    const int wid  = t >> 5;
    const int lane = t & 31;
    const int g  = lane >> 2;      // 0..7
    const int tg = lane & 3;       // 0..3

    const int ntiles = (n + 15) >> 4;
    const int tile = blockIdx.x * NWARP + wid;
    if (tile < ntiles) {
        const int node0 = tile << 4;
        const int r0 = node0 + g;
        const int r1 = node0 + g + 8;
        const int ra = (r0 < n) ? r0 : n;     // clamp to zero sentinel row
        const int rb = (r1 < n) ? r1 : n;

        float dacc[8][4];
#pragma unroll
        for (int nb = 0; nb < 8; nb++) {
            int c0 = nb * 8 + tg * 2;
            float bz0 = __ldg(bias + c0);
            float bz1 = __ldg(bias + c0 + 1);
            dacc[nb][0] = bz0; dacc[nb][1] = bz1;
            dacc[nb][2] = bz0; dacc[nb][3] = bz1;
        }

        const __half* Ar0 = g_A + (size_t)ra * AC;
        const __half* Ar1 = g_A + (size_t)rb * AC;

#pragma unroll
        for (int kc = 0; kc < 8; kc++) {
            int kb = kc * 16;
            const __half* pa = Ar0 + kb + tg * 2;
            const __half* pb = Ar1 + kb + tg * 2;
            uint32_t a0 = *reinterpret_cast<const uint32_t*>(pa);
            uint32_t a1 = *reinterpret_cast<const uint32_t*>(pb);
            uint32_t a2 = *reinterpret_cast<const uint32_t*>(pa + 8);
            uint32_t a3 = *reinterpret_cast<const uint32_t*>(pb + 8);
#pragma unroll
            for (int nb = 0; nb < 8; nb++) {
                const __half* bp = sB + (nb * 8 + g) * BSTRIDE + kb + tg * 2;
                uint32_t b0 = *reinterpret_cast<const uint32_t*>(bp);
                uint32_t b1 = *reinterpret_cast<const uint32_t*>(bp + 8);
                mma16816(dacc[nb], a0, a1, a2, a3, b0, b1);
            }
        }

#pragma unroll
        for (int nb = 0; nb < 8; nb++) {
            int c0 = nb * 8 + tg * 2;
            float v0 = dacc[nb][0], v1 = dacc[nb][1];
            float v2 = dacc[nb][2], v3 = dacc[nb][3];
            if (RELU) {
                v0 = fmaxf(v0, 0.f); v1 = fmaxf(v1, 0.f);
                v2 = fmaxf(v2, 0.f); v3 = fmaxf(v3, 0.f);
            }
            if (OUT16) {
                __half2 h01 = __floats2half2_rn(v0, v1);
                __half2 h23 = __floats2half2_rn(v2, v3);
                if (r0 < n)
                    *reinterpret_cast<__half2*>(
                        g_A + (size_t)r0 * AC + c0) = h01;
                if (r1 < n)
                    *reinterpret_cast<__half2*>(
                        g_A + (size_t)r1 * AC + c0) = h23;
            } else {
                if (r0 < n)
                    *reinterpret_cast<float2*>(
                        out + (size_t)r0 * D + c0) = make_float2(v0, v1);
                if (r1 < n)
                    *reinterpret_cast<float2*>(
                        out + (size_t)r1 * D + c0) = make_float2(v2, v3);
            }
        }
    }
    __syncthreads();
}

// ---------------------------------------------------------------------------
__global__ void __launch_bounds__(NTHR)
sage_kernel(const float* __restrict__ x,
            const int* __restrict__ src,
            const int* __restrict__ dst,
            const float* __restrict__ W1s, const float* __restrict__ W1n,
            const float* __restrict__ b1,
            const float* __restrict__ W2s, const float* __restrict__ W2n,
            const float* __restrict__ b2,
            float* __restrict__ out, int n, int E) {
    __shared__ __half sB[D * BSTRIDE];       // 17408 B (B matrix / reused)
    __shared__ int    sScan[NTHR];
    __shared__ int    sPart[NBLK];

    unsigned sense = 0;
    const int tid_g = blockIdx.x * NTHR + threadIdx.x;
    const int gstride = NBLK * NTHR;
    const int t = threadIdx.x;

    // ---- phase 0: x -> g_A cols 0..63 (fp16), zero row n, zero counters ----
    {
        int total16 = n * 16;                 // float4 chunks of x
        for (int i = tid_g; i < total16; i += gstride) {
            int row = i >> 4, c4 = (i & 15) * 4;
            float4 v = reinterpret_cast<const float4*>(x)[i];
            __half2 h0 = __floats2half2_rn(v.x, v.y);
            __half2 h1 = __floats2half2_rn(v.z, v.w);
            uint2 w;
            w.x = *reinterpret_cast<unsigned*>(&h0);
            w.y = *reinterpret_cast<unsigned*>(&h1);
            *reinterpret_cast<uint2*>(g_A + (size_t)row * AC + c4) = w;
        }
        for (int i = tid_g; i < n; i += gstride) g_cnt[i] = 0;
        if (blockIdx.x == 0 && t < AC / 2) {
            __half2 z = __floats2half2_rn(0.f, 0.f);
            reinterpret_cast<__half2*>(g_A + (size_t)n * AC)[t] = z;
        }
    }
    grid_barrier(sense);

    // ---- phase 1: histogram + rank capture ----
    for (int e = tid_g; e < E; e += gstride)
        g_rank[e] = atomicAdd(&g_cnt[__ldg(dst + e)], 1);
    grid_barrier(sense);

    // ---- phase 2a: block-local exclusive scan of padded counts ----
    const int chunk = (n + NBLK - 1) / NBLK;      // 338 <= NTHR
    const int node = blockIdx.x * chunk + t;
    int padded = 0;
    if (t < chunk && node < n) padded = (g_cnt[node] + 7) & ~7;
    sScan[t] = padded;
    __syncthreads();
    for (int off = 1; off < NTHR; off <<= 1) {
        int v = (t >= off) ? sScan[t - off] : 0;
        __syncthreads();
        sScan[t] += v;
        __syncthreads();
    }
    int excl = sScan[t] - padded;
    if (t == NTHR - 1) g_part[blockIdx.x] = sScan[NTHR - 1];
    grid_barrier(sense);

    // ---- phase 2b: global base + rowstart + sentinel padding edges ----
    {
        if (t < NBLK) sPart[t] = g_part[t];
        __syncthreads();
        int base = 0;
        for (int b = 0; b < blockIdx.x; b++) base += sPart[b];
        if (t < chunk && node < n) {
            int rs = base + excl;
            g_rowstart[node] = rs;
            int cnt = g_cnt[node];
            int degp = (cnt + 7) & ~7;
            for (int j = cnt; j < degp; j++) g_edge[rs + j] = n;
        }
    }
    grid_barrier(sense);

    // ---- phase 3: fill CSR (atomic-free) ----
    for (int e = tid_g; e < E; e += gstride) {
        int d = __ldg(dst + e);
        g_edge[g_rowstart[d] + g_rank[e]] = __ldg(src + e);
    }
    grid_barrier(sense);

    // ---- phase 4: gather layer 1 ----
    gather_phase(n);
    grid_barrier(sense);

    // ---- phase 5: combine layer 1 (relu) -> h1 fp16 into g_A ----
    combine_phase<true, true>(W1s, W1n, b1, nullptr, n, sB);
    grid_barrier(sense);

    // ---- phase 6: gather layer 2 ----
    gather_phase(n);
    grid_barrier(sense);

    // ---- phase 7: combine layer 2 -> out fp32 ----
    combine_phase<false, false>(W2s, W2n, b2, out, n, sB);
}

// ---------------------------------------------------------------------------
extern "C" void kernel_launch(void* const* d_in, const int* in_sizes, int n_in,
                              void* d_out, int out_size) {
    const float* x        = (const float*)d_in[0];
    const int*   src      = (const int*)d_in[1];
    const int*   dst      = (const int*)d_in[2];
    const float* W1_self  = (const float*)d_in[3];
    const float* W1_neigh = (const float*)d_in[4];
    const float* b1       = (const float*)d_in[5];
    const float* W2_self  = (const float*)d_in[6];
    const float* W2_neigh = (const float*)d_in[7];
    const float* b2       = (const float*)d_in[8];
    float* out = (float*)d_out;

    int n = in_sizes[0] / D;
    int E = in_sizes[1];

    sage_kernel<<<NBLK, NTHR>>>(x, src, dst,
                                W1_self, W1_neigh, b1,
                                W2_self, W2_neigh, b2,
                                out, n, E);
}